// round 2
// baseline (speedup 1.0000x reference)
#include <cuda_runtime.h>

// Problem constants (hardcoded from reference: x [4,256,256,256], WS=8, 8 heads)
#define BB    4
#define CC    256
#define HH    256
#define WW2   256
#define HW    65536          // HH*WW2
#define NPIX  262144         // BB*HW
#define NTILE 2048           // NPIX/128
#define HEADS 8
#define HD    32
#define NWIN  1024           // (HH/8)*(WW2/8)

// Scratch: q, k, v, attention-output, each [B][C][H][W] fp32 (256 MB each).
__device__ float g_q [BB * CC * HW];
__device__ float g_k [BB * CC * HW];
__device__ float g_v [BB * CC * HW];
__device__ float g_ao[BB * CC * HW];

// ---------------------------------------------------------------------------
// Tiled SGEMM: Out[m, p] = sum_k Wm[m, k] * X[k, p]
// X, Out in [B][C][HW] layout; p flattened over (b, hw). Block tile 128x128,
// K-chunks of 16, 256 threads, 8x8 register micro-tile (2x2 groups of 4).
// ---------------------------------------------------------------------------
__device__ __forceinline__ void gemm128(const float* __restrict__ Wm,
                                        const float* __restrict__ X,
                                        float* __restrict__ Out,
                                        int mBase, int pTile)
{
    __shared__ float xs[16][128];
    __shared__ float ws[16][132];   // pad to 132 (16B-aligned rows, fewer store conflicts)

    const int p0  = pTile * 128;
    const int b   = p0 >> 16;        // HW = 65536
    const int hw0 = p0 & (HW - 1);
    const float* Xb = X   + (size_t)b * CC * HW + hw0;
    float*       Ob = Out + (size_t)b * CC * HW + hw0;

    const int tid = threadIdx.x;
    const int tx  = tid & 15;   // column group (pixels)
    const int ty  = tid >> 4;   // row group (out channels)

    float acc[8][8];
#pragma unroll
    for (int i = 0; i < 8; i++)
#pragma unroll
        for (int j = 0; j < 8; j++) acc[i][j] = 0.f;

    for (int kb = 0; kb < CC; kb += 16) {
        // xs[k][p]: 512 float4 loads, coalesced along pixels
#pragma unroll
        for (int u = 0; u < 2; u++) {
            int f  = tid + u * 256;
            int kk = f >> 5;
            int p4 = (f & 31) * 4;
            float4 v = *reinterpret_cast<const float4*>(Xb + (size_t)(kb + kk) * HW + p4);
            *reinterpret_cast<float4*>(&xs[kk][p4]) = v;
        }
        // ws[k][m] = Wm[mBase+m][kb+k] (transpose on store)
#pragma unroll
        for (int u = 0; u < 2; u++) {
            int f  = tid + u * 256;
            int m  = f >> 2;
            int k4 = (f & 3) * 4;
            float4 v = *reinterpret_cast<const float4*>(Wm + (size_t)(mBase + m) * CC + kb + k4);
            ws[k4 + 0][m] = v.x; ws[k4 + 1][m] = v.y;
            ws[k4 + 2][m] = v.z; ws[k4 + 3][m] = v.w;
        }
        __syncthreads();

#pragma unroll
        for (int kk = 0; kk < 16; kk++) {
            float a[8], bv[8];
            float4 a0 = *reinterpret_cast<const float4*>(&ws[kk][ty * 4]);
            float4 a1 = *reinterpret_cast<const float4*>(&ws[kk][64 + ty * 4]);
            float4 b0 = *reinterpret_cast<const float4*>(&xs[kk][tx * 4]);
            float4 b1 = *reinterpret_cast<const float4*>(&xs[kk][64 + tx * 4]);
            a[0]=a0.x; a[1]=a0.y; a[2]=a0.z; a[3]=a0.w;
            a[4]=a1.x; a[5]=a1.y; a[6]=a1.z; a[7]=a1.w;
            bv[0]=b0.x; bv[1]=b0.y; bv[2]=b0.z; bv[3]=b0.w;
            bv[4]=b1.x; bv[5]=b1.y; bv[6]=b1.z; bv[7]=b1.w;
#pragma unroll
            for (int i = 0; i < 8; i++)
#pragma unroll
                for (int j = 0; j < 8; j++)
                    acc[i][j] += a[i] * bv[j];
        }
        __syncthreads();
    }

#pragma unroll
    for (int i = 0; i < 8; i++) {
        int m = mBase + ((i < 4) ? (ty * 4 + i) : (64 + ty * 4 + (i - 4)));
        float* orow = Ob + (size_t)m * HW;
        float4 v0 = make_float4(acc[i][0], acc[i][1], acc[i][2], acc[i][3]);
        float4 v1 = make_float4(acc[i][4], acc[i][5], acc[i][6], acc[i][7]);
        *reinterpret_cast<float4*>(orow + tx * 4)      = v0;
        *reinterpret_cast<float4*>(orow + 64 + tx * 4) = v1;
    }
}

// QKV projection: grid (NTILE, 6). y>>1 selects matrix, y&1 selects m-half.
__global__ __launch_bounds__(256) void qkv_kernel(const float* __restrict__ x,
                                                  const float* __restrict__ Wq,
                                                  const float* __restrict__ Wk,
                                                  const float* __restrict__ Wv)
{
    int mat = blockIdx.y >> 1;
    const float* Wm = (mat == 0) ? Wq : (mat == 1) ? Wk : Wv;
    float* Out      = (mat == 0) ? g_q : (mat == 1) ? g_k : g_v;
    gemm128(Wm, x, Out, (blockIdx.y & 1) * 128, blockIdx.x);
}

// Output projection: grid (NTILE, 2)
__global__ __launch_bounds__(256) void wo_kernel(const float* __restrict__ Wo,
                                                 float* __restrict__ out)
{
    gemm128(Wo, g_ao, out, blockIdx.y * 128, blockIdx.x);
}

// ---------------------------------------------------------------------------
// Windowed attention: one block per (batch, window, head). 64 threads; thread i
// owns query token i: computes S[i,:] (len-64 dots over hd=32), softmax in
// registers, then O[:, i]. Smem tiles are channel-major [32][64] so the inner
// loops read broadcast float4s (1 LDS.128 per 4 FMA).
// ---------------------------------------------------------------------------
__global__ __launch_bounds__(64) void attn_kernel()
{
    __shared__ float qs[HD][64];
    __shared__ float ks[HD][64];
    __shared__ float vs[HD][64];

    const int bidx = blockIdx.x;
    const int head = bidx & 7;
    const int win  = bidx >> 3;
    const int b    = win >> 10;          // NWIN = 1024
    const int wh   = (win >> 5) & 31;
    const int ww   = win & 31;
    const int tid  = threadIdx.x;

    const size_t base = (size_t)b * CC * HW + (size_t)(head * HD) * HW
                      + (size_t)(wh * 8) * WW2 + (size_t)(ww * 8);

    {   // load q/k/v window tiles: lane = token j, loop over channels
        const int j = tid;
        const int r = j >> 3, s = j & 7;
        const size_t off = base + (size_t)r * WW2 + s;
#pragma unroll
        for (int c = 0; c < HD; c++) {
            size_t a = off + (size_t)c * HW;
            qs[c][j] = g_q[a];
            ks[c][j] = g_k[a];
            vs[c][j] = g_v[a];
        }
    }
    __syncthreads();

    const int i = tid;
    float s[64];
#pragma unroll
    for (int j = 0; j < 64; j++) s[j] = 0.f;

#pragma unroll
    for (int c = 0; c < HD; c++) {
        float qv = qs[c][i];
#pragma unroll
        for (int j4 = 0; j4 < 16; j4++) {
            float4 kv = *reinterpret_cast<const float4*>(&ks[c][j4 * 4]);
            s[4 * j4 + 0] += qv * kv.x;
            s[4 * j4 + 1] += qv * kv.y;
            s[4 * j4 + 2] += qv * kv.z;
            s[4 * j4 + 3] += qv * kv.w;
        }
    }

    const float scale = 0.17677669529663687f;   // 32^-0.5
    float mx = -1e30f;
#pragma unroll
    for (int j = 0; j < 64; j++) { s[j] *= scale; mx = fmaxf(mx, s[j]); }
    float sum = 0.f;
#pragma unroll
    for (int j = 0; j < 64; j++) { s[j] = __expf(s[j] - mx); sum += s[j]; }
    float inv = 1.f / sum;
#pragma unroll
    for (int j = 0; j < 64; j++) s[j] *= inv;

    const int r = i >> 3, sc = i & 7;
    const size_t obase = base + (size_t)r * WW2 + sc;
#pragma unroll
    for (int c = 0; c < HD; c++) {
        float accv = 0.f;
#pragma unroll
        for (int j4 = 0; j4 < 16; j4++) {
            float4 vv = *reinterpret_cast<const float4*>(&vs[c][j4 * 4]);
            accv += s[4 * j4 + 0] * vv.x + s[4 * j4 + 1] * vv.y
                  + s[4 * j4 + 2] * vv.z + s[4 * j4 + 3] * vv.w;
        }
        g_ao[obase + (size_t)c * HW] = accv;
    }
}

// ---------------------------------------------------------------------------
extern "C" void kernel_launch(void* const* d_in, const int* in_sizes, int n_in,
                              void* d_out, int out_size)
{
    const float* x  = (const float*)d_in[0];
    const float* Wq = (const float*)d_in[1];
    const float* Wk = (const float*)d_in[2];
    const float* Wv = (const float*)d_in[3];
    const float* Wo = (const float*)d_in[4];
    float* out = (float*)d_out;

    qkv_kernel<<<dim3(NTILE, 6), 256>>>(x, Wq, Wk, Wv);
    attn_kernel<<<BB * NWIN * HEADS, 64>>>();
    wo_kernel<<<dim3(NTILE, 2), 256>>>(Wo, out);
}

// round 4
// speedup vs baseline: 1.9895x; 1.9895x over previous
#include <cuda_runtime.h>
#include <cstdint>

#define BB    4
#define CC    256
#define HH    256
#define WW2   256
#define HW    65536          // HH*WW2
#define NPIX  262144         // BB*HW
#define NTILE 2048           // NPIX/128
#define HEADS 8
#define HD    32
#define NWIN  1024           // (HH/8)*(WW2/8)

// Scratch: q, k, v, attention-output, each [B][C][H][W] fp32 (256 MB each).
__device__ float g_q [BB * CC * HW];
__device__ float g_k [BB * CC * HW];
__device__ float g_v [BB * CC * HW];
__device__ float g_ao[BB * CC * HW];

// Pre-swizzled weights in mma-fragment order (tf32 bits).
// Layout: [mat(4)][mtile(16)][ktile(32)][lane(32)][slot(4)]
__device__ uint32_t g_swzW[4 * 16 * 32 * 128];

__device__ __forceinline__ uint32_t f2tf32(float f) {
    uint32_t u;
    asm("cvt.rna.tf32.f32 %0, %1;" : "=r"(u) : "f"(f));
    return u;
}

__device__ __forceinline__ void mma_tf32(float& c0, float& c1, float& c2, float& c3,
                                         uint32_t a0, uint32_t a1, uint32_t a2, uint32_t a3,
                                         uint32_t b0, uint32_t b1) {
    asm volatile(
        "mma.sync.aligned.m16n8k8.row.col.f32.tf32.tf32.f32 "
        "{%0,%1,%2,%3}, {%4,%5,%6,%7}, {%8,%9}, {%0,%1,%2,%3};\n"
        : "+f"(c0), "+f"(c1), "+f"(c2), "+f"(c3)
        : "r"(a0), "r"(a1), "r"(a2), "r"(a3), "r"(b0), "r"(b1));
}

// ---------------------------------------------------------------------------
// One-shot weight pre-swizzle: W[m][k] (row-major 256x256) -> fragment order.
// Fragment (m16n8k8 A, row-major): a_s at (r,c): r=(lane>>2)+(s&1)*8,
// c=(lane&3)+((s>>1))*4 within the 16x8 tile.
// ---------------------------------------------------------------------------
__global__ __launch_bounds__(256) void swz_kernel(const float* __restrict__ Wq,
                                                  const float* __restrict__ Wk,
                                                  const float* __restrict__ Wv,
                                                  const float* __restrict__ Wo)
{
    int idx = blockIdx.x * 256 + threadIdx.x;      // 65536 total
    int lane = idx & 31;
    int kt   = (idx >> 5) & 31;
    int mt   = (idx >> 10) & 15;
    int mat  = idx >> 14;
    const float* W = (mat == 0) ? Wq : (mat == 1) ? Wk : (mat == 2) ? Wv : Wo;

    uint32_t o[4];
#pragma unroll
    for (int s = 0; s < 4; s++) {
        int r = (lane >> 2) + (s & 1) * 8;
        int c = (lane & 3) + (s >> 1) * 4;
        o[s] = f2tf32(W[(mt * 16 + r) * CC + kt * 8 + c]);
    }
    uint4* dst = reinterpret_cast<uint4*>(&g_swzW[(size_t)idx * 4]);
    *dst = make_uint4(o[0], o[1], o[2], o[3]);
}

// ---------------------------------------------------------------------------
// tf32 tensor-core GEMM: Out[m, p] = sum_k W[m, k] * X[k, p]
// Block tile 128(m) x 128(p), K-chunk 16, double-buffered.
// 8 warps: wm = w&1 (two 64-row halves), wn = w>>2... (w>>1, four 32-col strips)
// Warp tile 64x32 -> 4 mtiles x 4 ntiles of m16n8k8.
// ---------------------------------------------------------------------------
__device__ __forceinline__ void gemm_tc(const uint32_t* __restrict__ Wz,   // swizzled base for this mat+mhalf
                                        const float* __restrict__ X,
                                        float* __restrict__ Out,
                                        int mBase, int pTile)
{
    __shared__ uint32_t As[2][2112];   // 16 tiles (kt*8+mt) x 132 (128 + pad4)
    __shared__ uint32_t Bs[2][2112];   // 32 tiles (kt*16+nt) x 66 (64 + pad2)

    const int tid  = threadIdx.x;
    const int w    = tid >> 5;
    const int lane = tid & 31;
    const int wm   = w & 1;
    const int wn   = w >> 1;

    const int p0  = pTile * 128;
    const int b   = p0 >> 16;
    const int hw0 = p0 & (HW - 1);
    const float* Xb = X   + (size_t)b * CC * HW + hw0;
    float*       Ob = Out + (size_t)b * CC * HW + hw0;

    float acc[4][4][4];
#pragma unroll
    for (int i = 0; i < 4; i++)
#pragma unroll
        for (int j = 0; j < 4; j++)
#pragma unroll
            for (int e = 0; e < 4; e++) acc[i][j][e] = 0.f;

    uint4  aR[2];
    float4 bR[2];

    // ---- staging helpers (inlined manually via macros-as-lambdas) ----
    auto ldgA = [&](int kc) {
#pragma unroll
        for (int u = 0; u < 2; u++) {
            int j = tid + u * 256;          // 512 uint4 total
            int t = j >> 5;                 // tile idx: kt*8+mt
            int l = j & 31;
            int ktl = t >> 3, mt = t & 7;
            aR[u] = *reinterpret_cast<const uint4*>(
                Wz + ((size_t)mt * 32 + (size_t)(kc * 2 + ktl)) * 128 + l * 4);
        }
    };
    auto stsA = [&](int buf) {
#pragma unroll
        for (int u = 0; u < 2; u++) {
            int j = tid + u * 256;
            int t = j >> 5;
            int l = j & 31;
            *reinterpret_cast<uint4*>(&As[buf][t * 132 + l * 4]) = aR[u];
        }
    };
    auto ldgB = [&](int kc) {
#pragma unroll
        for (int u = 0; u < 2; u++) {
            int j = tid + u * 256;          // 512 float4 total (16k x 128p)
            int k  = j >> 5;
            int p4 = (j & 31) * 4;
            bR[u] = *reinterpret_cast<const float4*>(Xb + (size_t)(kc * 16 + k) * HW + p4);
        }
    };
    auto stsB = [&](int buf) {
#pragma unroll
        for (int u = 0; u < 2; u++) {
            int j = tid + u * 256;
            int k  = j >> 5;
            int p4 = (j & 31) * 4;
            int ktl = k >> 3;
            int ch  = k & 7;
            int slot = ch >> 2;
            int cl   = ch & 3;
            float vals[4] = {bR[u].x, bR[u].y, bR[u].z, bR[u].w};
#pragma unroll
            for (int e = 0; e < 4; e++) {
                int p  = p4 + e;
                int nt = p >> 3;
                int n  = p & 7;
                int l2 = n * 4 + cl;
                Bs[buf][(ktl * 16 + nt) * 66 + l2 * 2 + slot] = f2tf32(vals[e]);
            }
        }
    };
    auto domma = [&](int buf) {
#pragma unroll
        for (int kt = 0; kt < 2; kt++) {
            uint4 a[4];
            uint2 bb[4];
#pragma unroll
            for (int mt = 0; mt < 4; mt++)
                a[mt] = *reinterpret_cast<const uint4*>(
                    &As[buf][(kt * 8 + wm * 4 + mt) * 132 + lane * 4]);
#pragma unroll
            for (int nt = 0; nt < 4; nt++)
                bb[nt] = *reinterpret_cast<const uint2*>(
                    &Bs[buf][(kt * 16 + wn * 4 + nt) * 66 + lane * 2]);
#pragma unroll
            for (int mt = 0; mt < 4; mt++)
#pragma unroll
                for (int nt = 0; nt < 4; nt++)
                    mma_tf32(acc[mt][nt][0], acc[mt][nt][1], acc[mt][nt][2], acc[mt][nt][3],
                             a[mt].x, a[mt].y, a[mt].z, a[mt].w, bb[nt].x, bb[nt].y);
        }
    };

    // ---- main pipeline: 16 K-chunks of 16 ----
    ldgA(0); ldgB(0);
    stsA(0); stsB(0);
    __syncthreads();
#pragma unroll 1
    for (int kc = 0; kc < 16; kc++) {
        if (kc < 15) { ldgA(kc + 1); ldgB(kc + 1); }
        domma(kc & 1);
        if (kc < 15) {
            stsA((kc + 1) & 1); stsB((kc + 1) & 1);
            __syncthreads();
        }
    }

    // ---- epilogue: fragment C layout -> global fp32 ----
#pragma unroll
    for (int mt = 0; mt < 4; mt++) {
#pragma unroll
        for (int nt = 0; nt < 4; nt++) {
            int m   = mBase + wm * 64 + mt * 16 + (lane >> 2);
            int col = wn * 32 + nt * 8 + (lane & 3) * 2;
            float* r0 = Ob + (size_t)m * HW + col;
            *reinterpret_cast<float2*>(r0) = make_float2(acc[mt][nt][0], acc[mt][nt][1]);
            *reinterpret_cast<float2*>(r0 + (size_t)8 * HW) =
                make_float2(acc[mt][nt][2], acc[mt][nt][3]);
        }
    }
}

__global__ __launch_bounds__(256, 2) void qkv_kernel(const float* __restrict__ x)
{
    int mat   = blockIdx.y >> 1;
    int mhalf = blockIdx.y & 1;
    float* Out = (mat == 0) ? g_q : (mat == 1) ? g_k : g_v;
    const uint32_t* Wz = g_swzW + ((size_t)mat * 16 + mhalf * 8) * 32 * 128;
    gemm_tc(Wz, x, Out, mhalf * 128, blockIdx.x);
}

__global__ __launch_bounds__(256, 2) void wo_kernel(float* __restrict__ out)
{
    int mhalf = blockIdx.y;
    const uint32_t* Wz = g_swzW + ((size_t)3 * 16 + mhalf * 8) * 32 * 128;
    gemm_tc(Wz, g_ao, out, mhalf * 128, blockIdx.x);
}

// ---------------------------------------------------------------------------
// Windowed attention: one block per (batch, window, head). 64 threads; thread i
// owns query token i. K/V tiles stored TOKEN-major in smem so inner loops do
// warp-broadcast LDS.128 (conflict-free, 1 phase). q, scores, output all in regs.
// ---------------------------------------------------------------------------
__global__ __launch_bounds__(64) void attn_kernel()
{
    __shared__ float ks2[64 * 36];   // [token][channel], stride 36 (16B-aligned rows)
    __shared__ float vs2[64 * 36];

    const int bidx = blockIdx.x;
    const int head = bidx & 7;
    const int win  = bidx >> 3;
    const int b    = win >> 10;
    const int wh   = (win >> 5) & 31;
    const int ww   = win & 31;
    const int tid  = threadIdx.x;

    const size_t base = (size_t)b * CC * HW + (size_t)(head * HD) * HW
                      + (size_t)(wh * 8) * WW2 + (size_t)(ww * 8);

    // load K/V token-major (coalesced global reads; ~4-way STS conflicts, cheap)
    {
        const int j = tid;
        const int r = j >> 3, sj = j & 7;
        const size_t off = base + (size_t)r * WW2 + sj;
#pragma unroll
        for (int c = 0; c < HD; c++) {
            size_t a = off + (size_t)c * HW;
            ks2[j * 36 + c] = g_k[a];
            vs2[j * 36 + c] = g_v[a];
        }
    }

    // q for own token -> registers
    const int i = tid;
    const int ri = i >> 3, si = i & 7;
    const size_t qoff = base + (size_t)ri * WW2 + si;
    float q[HD];
#pragma unroll
    for (int c = 0; c < HD; c++) q[c] = g_q[qoff + (size_t)c * HW];

    __syncthreads();

    // S[i, :] : 4 key columns at a time, broadcast LDS.128
    float s[64];
#pragma unroll
    for (int j0 = 0; j0 < 64; j0 += 4) {
        float a0 = 0.f, a1 = 0.f, a2 = 0.f, a3 = 0.f;
        const float4* k0 = reinterpret_cast<const float4*>(&ks2[(j0 + 0) * 36]);
        const float4* k1 = reinterpret_cast<const float4*>(&ks2[(j0 + 1) * 36]);
        const float4* k2 = reinterpret_cast<const float4*>(&ks2[(j0 + 2) * 36]);
        const float4* k3 = reinterpret_cast<const float4*>(&ks2[(j0 + 3) * 36]);
#pragma unroll
        for (int c4 = 0; c4 < 8; c4++) {
            float4 v0 = k0[c4], v1 = k1[c4], v2 = k2[c4], v3 = k3[c4];
            a0 += q[c4 * 4 + 0] * v0.x + q[c4 * 4 + 1] * v0.y + q[c4 * 4 + 2] * v0.z + q[c4 * 4 + 3] * v0.w;
            a1 += q[c4 * 4 + 0] * v1.x + q[c4 * 4 + 1] * v1.y + q[c4 * 4 + 2] * v1.z + q[c4 * 4 + 3] * v1.w;
            a2 += q[c4 * 4 + 0] * v2.x + q[c4 * 4 + 1] * v2.y + q[c4 * 4 + 2] * v2.z + q[c4 * 4 + 3] * v2.w;
            a3 += q[c4 * 4 + 0] * v3.x + q[c4 * 4 + 1] * v3.y + q[c4 * 4 + 2] * v3.z + q[c4 * 4 + 3] * v3.w;
        }
        s[j0] = a0; s[j0 + 1] = a1; s[j0 + 2] = a2; s[j0 + 3] = a3;
    }

    const float scale = 0.17677669529663687f;   // 32^-0.5
    float mx = -1e30f;
#pragma unroll
    for (int j = 0; j < 64; j++) { s[j] *= scale; mx = fmaxf(mx, s[j]); }
    float sum = 0.f;
#pragma unroll
    for (int j = 0; j < 64; j++) { s[j] = __expf(s[j] - mx); sum += s[j]; }
    float inv = 1.f / sum;
#pragma unroll
    for (int j = 0; j < 64; j++) s[j] *= inv;

    // O[:, i] = sum_j s[j] * V[:, j] : broadcast LDS.128, 32 independent accs
    float o[HD];
#pragma unroll
    for (int c = 0; c < HD; c++) o[c] = 0.f;
#pragma unroll
    for (int j = 0; j < 64; j++) {
        float sj = s[j];
        const float4* vp = reinterpret_cast<const float4*>(&vs2[j * 36]);
#pragma unroll
        for (int c4 = 0; c4 < 8; c4++) {
            float4 vv = vp[c4];
            o[c4 * 4 + 0] += sj * vv.x;
            o[c4 * 4 + 1] += sj * vv.y;
            o[c4 * 4 + 2] += sj * vv.z;
            o[c4 * 4 + 3] += sj * vv.w;
        }
    }

#pragma unroll
    for (int c = 0; c < HD; c++) g_ao[qoff + (size_t)c * HW] = o[c];
}

// ---------------------------------------------------------------------------
extern "C" void kernel_launch(void* const* d_in, const int* in_sizes, int n_in,
                              void* d_out, int out_size)
{
    const float* x  = (const float*)d_in[0];
    const float* Wq = (const float*)d_in[1];
    const float* Wk = (const float*)d_in[2];
    const float* Wv = (const float*)d_in[3];
    const float* Wo = (const float*)d_in[4];
    float* out = (float*)d_out;

    swz_kernel<<<256, 256>>>(Wq, Wk, Wv, Wo);
    qkv_kernel<<<dim3(NTILE, 6), 256>>>(x);
    attn_kernel<<<BB * NWIN * HEADS, 64>>>();
    wo_kernel<<<dim3(NTILE, 2), 256>>>(out);
}

// round 9
// speedup vs baseline: 2.3884x; 1.2005x over previous
#include <cuda_runtime.h>
#include <cstdint>

#define BB    4
#define CC    256
#define HH    256
#define WW2   256
#define HW    65536          // HH*WW2
#define NPIX  262144         // BB*HW
#define NTILE 2048           // NPIX/128
#define HEADS 8
#define HD    32
#define NWIN  1024           // (HH/8)*(WW2/8)

// Scratch: q, k, v, attention-output, each [B][C][H][W] fp32 (256 MB each).
__device__ float g_q [BB * CC * HW];
__device__ float g_k [BB * CC * HW];
__device__ float g_v [BB * CC * HW];
__device__ float g_ao[BB * CC * HW];

// Pre-swizzled weights in mma-fragment order (tf32 bits).
// Layout: [mat(4)][mtile(16)][ktile(32)][lane(32)][slot(4)]
__device__ uint32_t g_swzW[4 * 16 * 32 * 128];

__device__ __forceinline__ uint32_t f2tf32(float f) {
    uint32_t u;
    asm("cvt.rna.tf32.f32 %0, %1;" : "=r"(u) : "f"(f));
    return u;
}

__device__ __forceinline__ void mma_tf32(float& c0, float& c1, float& c2, float& c3,
                                         uint32_t a0, uint32_t a1, uint32_t a2, uint32_t a3,
                                         uint32_t b0, uint32_t b1) {
    asm volatile(
        "mma.sync.aligned.m16n8k8.row.col.f32.tf32.tf32.f32 "
        "{%0,%1,%2,%3}, {%4,%5,%6,%7}, {%8,%9}, {%0,%1,%2,%3};\n"
        : "+f"(c0), "+f"(c1), "+f"(c2), "+f"(c3)
        : "r"(a0), "r"(a1), "r"(a2), "r"(a3), "r"(b0), "r"(b1));
}

// ---------------------------------------------------------------------------
// One-shot weight pre-swizzle: W[m][k] (row-major 256x256) -> fragment order.
// ---------------------------------------------------------------------------
__global__ __launch_bounds__(256) void swz_kernel(const float* __restrict__ Wq,
                                                  const float* __restrict__ Wk,
                                                  const float* __restrict__ Wv,
                                                  const float* __restrict__ Wo)
{
    int idx = blockIdx.x * 256 + threadIdx.x;      // 65536 total
    int lane = idx & 31;
    int kt   = (idx >> 5) & 31;
    int mt   = (idx >> 10) & 15;
    int mat  = idx >> 14;
    const float* W = (mat == 0) ? Wq : (mat == 1) ? Wk : (mat == 2) ? Wv : Wo;

    uint32_t o[4];
#pragma unroll
    for (int s = 0; s < 4; s++) {
        int r = (lane >> 2) + (s & 1) * 8;
        int c = (lane & 3) + (s >> 1) * 4;
        o[s] = f2tf32(W[(mt * 16 + r) * CC + kt * 8 + c]);
    }
    uint4* dst = reinterpret_cast<uint4*>(&g_swzW[(size_t)idx * 4]);
    *dst = make_uint4(o[0], o[1], o[2], o[3]);
}

// ---------------------------------------------------------------------------
// tf32 tensor-core GEMM: Out[m, p] = sum_k W[m, k] * X[k, p]
// Block tile 128(m) x 128(p), K-chunk 16, double-buffered.
// B staging bank-conflict-reduced; XOR swizzle applied WITHIN the 64-entry
// tile offset (read side mirrors it with blx = (lane*2)^(lane&16)).
// ---------------------------------------------------------------------------
__device__ __forceinline__ void gemm_tc(const uint32_t* __restrict__ Wz,
                                        const float* __restrict__ X,
                                        float* __restrict__ Out,
                                        int mBase, int pTile)
{
    __shared__ uint32_t As[2][2112];   // 16 tiles (kt*8+mt) x 132
    __shared__ uint32_t Bs[2][2112];   // 32 tiles (kt*16+nt) x 66

    const int tid  = threadIdx.x;
    const int w    = tid >> 5;
    const int lane = tid & 31;
    const int wm   = w & 1;
    const int wn   = w >> 1;

    const int p0  = pTile * 128;
    const int b   = p0 >> 16;
    const int hw0 = p0 & (HW - 1);
    const float* Xb = X   + (size_t)b * CC * HW + hw0;
    float*       Ob = Out + (size_t)b * CC * HW + hw0;

    float acc[4][4][4];
#pragma unroll
    for (int i = 0; i < 4; i++)
#pragma unroll
        for (int j = 0; j < 4; j++)
#pragma unroll
            for (int e = 0; e < 4; e++) acc[i][j][e] = 0.f;

    uint4  aR[2];
    float4 bR[2];

    auto ldgA = [&](int kc) {
#pragma unroll
        for (int u = 0; u < 2; u++) {
            int j = tid + u * 256;
            int t = j >> 5;
            int l = j & 31;
            int ktl = t >> 3, mt = t & 7;
            aR[u] = *reinterpret_cast<const uint4*>(
                Wz + ((size_t)mt * 32 + (size_t)(kc * 2 + ktl)) * 128 + l * 4);
        }
    };
    auto stsA = [&](int buf) {
#pragma unroll
        for (int u = 0; u < 2; u++) {
            int j = tid + u * 256;
            int t = j >> 5;
            int l = j & 31;
            *reinterpret_cast<uint4*>(&As[buf][t * 132 + l * 4]) = aR[u];
        }
    };
    // warp wj covers k = {2*(wj&7), +1}; phalf = wj>>3 selects 64-col half
    auto ldgB = [&](int kc) {
#pragma unroll
        for (int u = 0; u < 2; u++) {
            int j  = tid + u * 256;
            int wj = j >> 5;
            int l  = j & 31;
            int h  = l >> 4;
            int m  = l & 15;
            int k  = 2 * (wj & 7) + h;
            int pf = ((wj >> 3) * 16 + m) * 4;
            bR[u] = *reinterpret_cast<const float4*>(Xb + (size_t)(kc * 16 + k) * HW + pf);
        }
    };
    auto stsB = [&](int buf) {
#pragma unroll
        for (int u = 0; u < 2; u++) {
            int j  = tid + u * 256;
            int wj = j >> 5;
            int l  = j & 31;
            int h  = l >> 4;
            int m  = l & 15;
            int k  = 2 * (wj & 7) + h;
            int pf = ((wj >> 3) * 16 + m) * 4;
            int ktl = k >> 3, ch = k & 7;
            int slot = ch >> 2, cl = ch & 3;
            int sl2 = slot ^ (cl & 1);
            float vals[4] = {bR[u].x, bR[u].y, bR[u].z, bR[u].w};
#pragma unroll
            for (int e = 0; e < 4; e++) {
                int p  = pf + e;
                int nt = p >> 3;
                int n  = p & 7;
                int off = (n * 4 + cl) * 2 + sl2;
                off ^= (n & 4) << 2;              // FIX: swizzle intra-tile offset only
                Bs[buf][(ktl * 16 + nt) * 66 + off] = f2tf32(vals[e]);
            }
        }
    };
    const int blx = (lane * 2) ^ (lane & 16);
    const bool bswap = (lane & 1);
    auto domma = [&](int buf) {
#pragma unroll
        for (int kt = 0; kt < 2; kt++) {
            uint4 a[4];
            uint32_t b0[4], b1[4];
#pragma unroll
            for (int mt = 0; mt < 4; mt++)
                a[mt] = *reinterpret_cast<const uint4*>(
                    &As[buf][(kt * 8 + wm * 4 + mt) * 132 + lane * 4]);
#pragma unroll
            for (int nt = 0; nt < 4; nt++) {
                uint2 raw = *reinterpret_cast<const uint2*>(
                    &Bs[buf][(kt * 16 + wn * 4 + nt) * 66 + blx]);
                b0[nt] = bswap ? raw.y : raw.x;
                b1[nt] = bswap ? raw.x : raw.y;
            }
#pragma unroll
            for (int mt = 0; mt < 4; mt++)
#pragma unroll
                for (int nt = 0; nt < 4; nt++)
                    mma_tf32(acc[mt][nt][0], acc[mt][nt][1], acc[mt][nt][2], acc[mt][nt][3],
                             a[mt].x, a[mt].y, a[mt].z, a[mt].w, b0[nt], b1[nt]);
        }
    };

    ldgA(0); ldgB(0);
    stsA(0); stsB(0);
    __syncthreads();
#pragma unroll 1
    for (int kc = 0; kc < 16; kc++) {
        if (kc < 15) { ldgA(kc + 1); ldgB(kc + 1); }
        domma(kc & 1);
        if (kc < 15) {
            stsA((kc + 1) & 1); stsB((kc + 1) & 1);
            __syncthreads();
        }
    }

#pragma unroll
    for (int mt = 0; mt < 4; mt++) {
#pragma unroll
        for (int nt = 0; nt < 4; nt++) {
            int m   = mBase + wm * 64 + mt * 16 + (lane >> 2);
            int col = wn * 32 + nt * 8 + (lane & 3) * 2;
            float* r0 = Ob + (size_t)m * HW + col;
            *reinterpret_cast<float2*>(r0) = make_float2(acc[mt][nt][0], acc[mt][nt][1]);
            *reinterpret_cast<float2*>(r0 + (size_t)8 * HW) =
                make_float2(acc[mt][nt][2], acc[mt][nt][3]);
        }
    }
}

__global__ __launch_bounds__(256, 2) void qkv_kernel(const float* __restrict__ x)
{
    int mat   = blockIdx.y >> 1;
    int mhalf = blockIdx.y & 1;
    float* Out = (mat == 0) ? g_q : (mat == 1) ? g_k : g_v;
    const uint32_t* Wz = g_swzW + ((size_t)mat * 16 + mhalf * 8) * 32 * 128;
    gemm_tc(Wz, x, Out, mhalf * 128, blockIdx.x);
}

__global__ __launch_bounds__(256, 2) void wo_kernel(float* __restrict__ out)
{
    int mhalf = blockIdx.y;
    const uint32_t* Wz = g_swzW + ((size_t)3 * 16 + mhalf * 8) * 32 * 128;
    gemm_tc(Wz, g_ao, out, mhalf * 128, blockIdx.x);
}

// ---------------------------------------------------------------------------
// Tensor-core windowed attention. Block = 64 threads = 2 warps = one
// (window, head). Warp w owns S/O rows [32w, 32w+32).
//   S = (scale*Q)^T K : m=32, n=64, k=32  (tf32 mma)
//   softmax on C fragments (quad shuffles), P -> smem (tf32)
//   O = P V^T : m=32, n=32, k=64; 1/rowsum folded into epilogue.
// Smem layouts for conflict-free fragment LDS:
//   Kt/Vt [c][j] stride 72, Q stride 36 + XOR-8 col swizzle, P stride 68.
// ---------------------------------------------------------------------------
__global__ __launch_bounds__(64) void attn_tc_kernel()
{
    __shared__ uint32_t Kt[32 * 72];
    __shared__ uint32_t Vt[32 * 72];
    __shared__ uint32_t Qw[2][32 * 36];
    __shared__ uint32_t Pw[2][32 * 68];

    const int bidx = blockIdx.x;
    const int head = bidx & 7;
    const int win  = bidx >> 3;
    const int b    = win >> 10;
    const int wh   = (win >> 5) & 31;
    const int ww   = win & 31;
    const int tid  = threadIdx.x;
    const int w    = tid >> 5;
    const int lane = tid & 31;

    const size_t base = (size_t)b * CC * HW + (size_t)(head * HD) * HW
                      + (size_t)(wh * 8) * WW2 + (size_t)(ww * 8);

    // ---- load: thread = token j ----
    {
        const int j = tid;
        const size_t off = base + (size_t)(j >> 3) * WW2 + (j & 7);
        const float scale = 0.17677669529663687f;   // 32^-0.5
        const int qsw = ((lane >> 3) & 3) << 3;
#pragma unroll
        for (int c = 0; c < HD; c++) {
            size_t a = off + (size_t)c * HW;
            Kt[c * 72 + j] = f2tf32(g_k[a]);
            Vt[c * 72 + j] = f2tf32(g_v[a]);
            Qw[w][lane * 36 + (c ^ qsw)] = f2tf32(g_q[a] * scale);
        }
    }
    __syncthreads();

    // ---- S = Q^T K ----
    float s[2][8][4];
#pragma unroll
    for (int mt = 0; mt < 2; mt++)
#pragma unroll
        for (int nt = 0; nt < 8; nt++)
#pragma unroll
            for (int e = 0; e < 4; e++) s[mt][nt][e] = 0.f;

#pragma unroll
    for (int kt = 0; kt < 4; kt++) {
        uint32_t a[2][4];
#pragma unroll
        for (int mt = 0; mt < 2; mt++)
#pragma unroll
            for (int sl = 0; sl < 4; sl++) {
                int ir = (lane >> 2) + 8 * (sl & 1) + 16 * mt;
                int c  = (lane & 3) + 4 * (sl >> 1) + 8 * kt;
                int ks = ((ir >> 3) & 3) << 3;
                a[mt][sl] = Qw[w][ir * 36 + (c ^ ks)];
            }
#pragma unroll
        for (int nt = 0; nt < 8; nt++) {
            int cb = 8 * kt + (lane & 3);
            int jj = 8 * nt + (lane >> 2);
            uint32_t b0 = Kt[cb * 72 + jj];
            uint32_t b1 = Kt[(cb + 4) * 72 + jj];
#pragma unroll
            for (int mt = 0; mt < 2; mt++)
                mma_tf32(s[mt][nt][0], s[mt][nt][1], s[mt][nt][2], s[mt][nt][3],
                         a[mt][0], a[mt][1], a[mt][2], a[mt][3], b0, b1);
        }
    }

    // ---- softmax (rows owned: [mt][hi] -> lane>>2 + 8*hi + 16*mt) ----
    float mx[2][2] = {{-1e30f, -1e30f}, {-1e30f, -1e30f}};
#pragma unroll
    for (int mt = 0; mt < 2; mt++)
#pragma unroll
        for (int nt = 0; nt < 8; nt++) {
            mx[mt][0] = fmaxf(mx[mt][0], fmaxf(s[mt][nt][0], s[mt][nt][1]));
            mx[mt][1] = fmaxf(mx[mt][1], fmaxf(s[mt][nt][2], s[mt][nt][3]));
        }
#pragma unroll
    for (int mt = 0; mt < 2; mt++)
#pragma unroll
        for (int hi = 0; hi < 2; hi++) {
            float v = mx[mt][hi];
            v = fmaxf(v, __shfl_xor_sync(0xffffffffu, v, 1));
            v = fmaxf(v, __shfl_xor_sync(0xffffffffu, v, 2));
            mx[mt][hi] = v;
        }
    float sum[2][2] = {{0.f, 0.f}, {0.f, 0.f}};
#pragma unroll
    for (int mt = 0; mt < 2; mt++)
#pragma unroll
        for (int nt = 0; nt < 8; nt++) {
#pragma unroll
            for (int e = 0; e < 4; e++) {
                float p = __expf(s[mt][nt][e] - mx[mt][e >> 1]);
                s[mt][nt][e] = p;
                sum[mt][e >> 1] += p;
            }
        }
    float inv[2][2];
#pragma unroll
    for (int mt = 0; mt < 2; mt++)
#pragma unroll
        for (int hi = 0; hi < 2; hi++) {
            float v = sum[mt][hi];
            v += __shfl_xor_sync(0xffffffffu, v, 1);
            v += __shfl_xor_sync(0xffffffffu, v, 2);
            inv[mt][hi] = 1.f / v;
        }

    // ---- P -> smem (tf32, unnormalized) ----
#pragma unroll
    for (int mt = 0; mt < 2; mt++)
#pragma unroll
        for (int nt = 0; nt < 8; nt++) {
            int rlo = (lane >> 2) + 16 * mt;
            int col = 2 * (lane & 3) + 8 * nt;
            uint2 lo = make_uint2(f2tf32(s[mt][nt][0]), f2tf32(s[mt][nt][1]));
            uint2 hi = make_uint2(f2tf32(s[mt][nt][2]), f2tf32(s[mt][nt][3]));
            *reinterpret_cast<uint2*>(&Pw[w][rlo * 68 + col]) = lo;
            *reinterpret_cast<uint2*>(&Pw[w][(rlo + 8) * 68 + col]) = hi;
        }
    __syncwarp();

    // ---- O = P V^T ----
    float o[2][4][4];
#pragma unroll
    for (int mt = 0; mt < 2; mt++)
#pragma unroll
        for (int nt = 0; nt < 4; nt++)
#pragma unroll
            for (int e = 0; e < 4; e++) o[mt][nt][e] = 0.f;

#pragma unroll
    for (int kt = 0; kt < 8; kt++) {
        uint32_t a[2][4];
#pragma unroll
        for (int mt = 0; mt < 2; mt++)
#pragma unroll
            for (int sl = 0; sl < 4; sl++) {
                int ir = (lane >> 2) + 8 * (sl & 1) + 16 * mt;
                int jj = (lane & 3) + 4 * (sl >> 1) + 8 * kt;
                a[mt][sl] = Pw[w][ir * 68 + jj];
            }
#pragma unroll
        for (int nt = 0; nt < 4; nt++) {
            int cc = 8 * nt + (lane >> 2);
            int jb = 8 * kt + (lane & 3);
            uint32_t b0 = Vt[cc * 72 + jb];
            uint32_t b1 = Vt[cc * 72 + jb + 4];
#pragma unroll
            for (int mt = 0; mt < 2; mt++)
                mma_tf32(o[mt][nt][0], o[mt][nt][1], o[mt][nt][2], o[mt][nt][3],
                         a[mt][0], a[mt][1], a[mt][2], a[mt][3], b0, b1);
        }
    }

    // ---- epilogue: scale by 1/rowsum, scatter to g_ao ----
#pragma unroll
    for (int mt = 0; mt < 2; mt++)
#pragma unroll
        for (int nt = 0; nt < 4; nt++)
#pragma unroll
            for (int e = 0; e < 4; e++) {
                int rp  = (lane >> 2) + 8 * (e >> 1) + 16 * mt;
                int tok = w * 32 + rp;
                int cl  = 2 * (lane & 3) + (e & 1) + 8 * nt;
                g_ao[base + (size_t)cl * HW + (size_t)(tok >> 3) * WW2 + (tok & 7)]
                    = o[mt][nt][e] * inv[mt][e >> 1];
            }
}

// ---------------------------------------------------------------------------
extern "C" void kernel_launch(void* const* d_in, const int* in_sizes, int n_in,
                              void* d_out, int out_size)
{
    const float* x  = (const float*)d_in[0];
    const float* Wq = (const float*)d_in[1];
    const float* Wk = (const float*)d_in[2];
    const float* Wv = (const float*)d_in[3];
    const float* Wo = (const float*)d_in[4];
    float* out = (float*)d_out;

    swz_kernel<<<256, 256>>>(Wq, Wk, Wv, Wo);
    qkv_kernel<<<dim3(NTILE, 6), 256>>>(x);
    attn_tc_kernel<<<BB * NWIN * HEADS, 64>>>();
    wo_kernel<<<dim3(NTILE, 2), 256>>>(out);
}